// round 8
// baseline (speedup 1.0000x reference)
#include <cuda_runtime.h>

#define DEC 256
#define FPSCALE 16777216.0f   // 2^24 fixed-point for deterministic accumulation

// Deterministic global accumulator (integer adds commute exactly) + ticket.
__device__ unsigned long long g_isum    = 0ULL;
__device__ int                g_counter = 0;

// Pad-swizzle: phys = j + (j>>4). For the lane pattern j = 4*lane + k this
// spreads accesses perfectly across all 16 float2-banks per phase.
__device__ __forceinline__ int swz(int j) { return j + (j >> 4); }

// All values in NEGATED space: n = (-o_i, -t_i), w = (-o_j, -t_j).
// dO = o_i - o_j = w.x - n.x ; dt = t_i - t_j = w.y - n.y.
__device__ __forceinline__ void pair_term(float2 n, float2 w, float& acc) {
    float dO = w.x - n.x;
    float dt = w.y - n.y;
    // x = sign(dt)*dO via one LOP3; dt==+-0 has weight 0 so sign is moot.
    float x = __uint_as_float(__float_as_uint(dO) ^
                              (__float_as_uint(dt) & 0x80000000u));
    float h = fmaxf(x + 1.0f, 0.0f);
    if (fabsf(dt) > 0.1f) acc += h;
}

__global__ void __launch_bounds__(256)
rank_loss_fused(const float* __restrict__ inp, const float* __restrict__ tm,
                float* __restrict__ out, float scale) {
    __shared__ float2 sh[544];     // negated (o,t), duplicated, pad-swizzled
    __shared__ float  warpsum[8];

    const int g    = blockIdx.x >> 1;   // group
    const int half = blockIdx.x & 1;    // k-tile: 0 -> k in [1..64], 1 -> [65..128]
    const int tid  = threadIdx.x;
    const int base = g * DEC;

    {
        float2 nv = make_float2(-inp[base + tid], -tm[base + tid]);
        sh[swz(tid)]       = nv;
        sh[swz(tid + DEC)] = nv;
    }
    __syncthreads();

    // 4 k-subranges (16 each) x 64 row-quads.
    const int s   = tid >> 6;
    const int tau = tid & 63;
    const int b   = tau * 4;                 // first owned row
    const int k0  = half * 64 + s * 16 + 1;  // k in [k0, k0+15]

    // Own rows, already negated, straight from shared (b..b+3 never cross a
    // 16-boundary so swz is contiguous here, but load as 4x float2 for safety).
    const float2 n0 = sh[swz(b + 0)];
    const float2 n1 = sh[swz(b + 1)];
    const float2 n2 = sh[swz(b + 2)];
    const float2 n3 = sh[swz(b + 3)];

    // Sliding window: w[r] = sh[b + k + r]
    float2 w0 = sh[swz(b + k0 + 0)];
    float2 w1 = sh[swz(b + k0 + 1)];
    float2 w2 = sh[swz(b + k0 + 2)];
    float2 w3 = sh[swz(b + k0 + 3)];

    float a0 = 0.0f, a1 = 0.0f, a2 = 0.0f, a3 = 0.0f;

    #pragma unroll
    for (int kk = 0; kk < 15; ++kk) {        // k = k0 .. k0+14, always active
        pair_term(n0, w0, a0);
        pair_term(n1, w1, a1);
        pair_term(n2, w2, a2);
        pair_term(n3, w3, a3);
        w0 = w1; w1 = w2; w2 = w3;           // renamed away after full unroll
        w3 = sh[swz(b + k0 + kk + 4)];
    }
    // Epilogue k = k0+15. Only k=128 (half==1, s==3) is restricted to rows<128,
    // i.e. inactive exactly when half==1 && tid >= 224.
    if (!(half && tid >= 224)) {
        pair_term(n0, w0, a0);
        pair_term(n1, w1, a1);
        pair_term(n2, w2, a2);
        pair_term(n3, w3, a3);
    }

    // Block reduction (fixed order).
    float ssum = (a0 + a1) + (a2 + a3);
    const int lane = tid & 31;
    const int w    = tid >> 5;
    #pragma unroll
    for (int off = 16; off; off >>= 1)
        ssum += __shfl_xor_sync(0xFFFFFFFFu, ssum, off);
    if (lane == 0) warpsum[w] = ssum;
    __syncthreads();

    if (tid == 0) {
        float bsum = 0.0f;
        #pragma unroll
        for (int j = 0; j < 8; ++j) bsum += warpsum[j];
        // Deterministic fixed-point accumulation (order-independent).
        unsigned long long q = (unsigned long long)llrintf(bsum * FPSCALE);
        atomicAdd(&g_isum, q);
        __threadfence();
        int c = atomicAdd(&g_counter, 1);
        if (c == (int)gridDim.x - 1) {
            unsigned long long tot = atomicAdd(&g_isum, 0ULL);
            out[0] = (float)((double)tot * (1.0 / (double)FPSCALE) * (double)scale);
            g_isum = 0ULL;                   // reset for next graph replay
            __threadfence();
            g_counter = 0;
        }
    }
}

extern "C" void kernel_launch(void* const* d_in, const int* in_sizes, int n_in,
                              void* d_out, int out_size) {
    const float* inp = (const float*)d_in[0];   // input, [B,1] fp32
    const float* tm  = (const float*)d_in[1];   // gdt_ts, [B]  fp32

    const int B = in_sizes[0];
    const int K = B / DEC;
    const int G = K - 1;                        // reference skips the last group
    const double N = (double)G * DEC * (DEC - 1);
    const float scale = (float)(2.0 / N);       // x2: unordered -> ordered pairs

    rank_loss_fused<<<2 * G, 256>>>(inp, tm, (float*)d_out, scale);
}

// round 10
// speedup vs baseline: 1.1633x; 1.1633x over previous
#include <cuda_runtime.h>

#define DEC 256
#define COPIES 4
#define CSTRIDE 385           // ≡ 1 (mod 16): each copy rotates banks by 1 pair
#define FPSCALE 16777216.0f   // 2^24 fixed-point for deterministic accumulation

// Deterministic global accumulator (integer adds commute exactly) + ticket.
__device__ unsigned long long g_isum    = 0ULL;
__device__ int                g_counter = 0;

// Pair term. nneg = (-o_i, -t_i) packed, w = (o_j, t_j) packed.
// d = w + nneg = (o_j - o_i, t_j - t_i) = (-dO, -dt); the sign-xor product
// x = sign(dt)*dO is invariant under joint negation, |dt| too.
__device__ __forceinline__ void pt(unsigned long long nneg, unsigned long long w,
                                   float& acc) {
    unsigned long long d;
    asm("add.rn.f32x2 %0, %1, %2;" : "=l"(d) : "l"(w), "l"(nneg));
    float dO = __uint_as_float((unsigned)d);          // low reg (free)
    float dt = __uint_as_float((unsigned)(d >> 32));  // high reg (free)
    float x  = __uint_as_float(__float_as_uint(dO) ^
                               (__float_as_uint(dt) & 0x80000000u));
    float h  = fmaxf(x + 1.0f, 0.0f);
    if (fabsf(dt) > 0.1f) acc += h;
}

__global__ void __launch_bounds__(256)
rank_loss_fused(const float* __restrict__ inp, const float* __restrict__ tm,
                float* __restrict__ out, float scale) {
    __shared__ unsigned long long sh4[COPIES * CSTRIDE];  // 4 copies, positive (o,t)
    __shared__ float warpsum[8];

    const int g    = blockIdx.x >> 1;   // group
    const int half = blockIdx.x & 1;    // k-tile: 0 -> k in [1..64], 1 -> [65..128]
    const int tid  = threadIdx.x;
    const int base = g * DEC;

    {
        float o = inp[base + tid];
        float t = tm[base + tid];
        unsigned long long v;
        asm("mov.b64 %0, {%1, %2};" : "=l"(v) : "f"(o), "f"(t));
        #pragma unroll
        for (int c = 0; c < COPIES; ++c) {
            sh4[c * CSTRIDE + tid] = v;
            if (tid < CSTRIDE - DEC)                  // wraparound dup (j <= 384)
                sh4[c * CSTRIDE + tid + DEC] = v;
        }
    }
    __syncthreads();

    // 4 k-subranges (16 each) x 64 row-quads.
    const int s   = tid >> 6;
    const int tau = tid & 63;
    const int b   = tau * 4;                 // first owned row
    const int k0  = half * 64 + s * 16 + 1;  // k in [k0, k0+15]

    // Per-lane copy selection -> stride-4 lane pattern is bank-conflict-free.
    const unsigned long long* my = &sh4[((tid >> 2) & 3) * CSTRIDE];

    // Own rows, negated once (one 64-bit xor each).
    const unsigned long long n0 = my[b + 0] ^ 0x8000000080000000ULL;
    const unsigned long long n1 = my[b + 1] ^ 0x8000000080000000ULL;
    const unsigned long long n2 = my[b + 2] ^ 0x8000000080000000ULL;
    const unsigned long long n3 = my[b + 3] ^ 0x8000000080000000ULL;

    // Circular 4-entry window, compile-time phase -> no register copies.
    unsigned long long W[4] = { my[b + k0 + 0], my[b + k0 + 1],
                                my[b + k0 + 2], my[b + k0 + 3] };

    float a0 = 0.0f, a1 = 0.0f, a2 = 0.0f, a3 = 0.0f;

    #pragma unroll
    for (int kk = 0; kk < 15; ++kk) {        // k = k0 .. k0+14, always active
        pt(n0, W[(kk + 0) & 3], a0);
        pt(n1, W[(kk + 1) & 3], a1);
        pt(n2, W[(kk + 2) & 3], a2);
        pt(n3, W[(kk + 3) & 3], a3);
        W[kk & 3] = my[b + k0 + kk + 4];     // immediate offset, zero addr ALU
    }
    // Epilogue k = k0+15. Only k=128 (half==1, s==3) is rows<128 restricted,
    // i.e. inactive exactly when half==1 && tid >= 224.
    if (!(half && tid >= 224)) {
        pt(n0, W[(15 + 0) & 3], a0);
        pt(n1, W[(15 + 1) & 3], a1);
        pt(n2, W[(15 + 2) & 3], a2);
        pt(n3, W[(15 + 3) & 3], a3);
    }

    // Block reduction (fixed order).
    float ssum = (a0 + a1) + (a2 + a3);
    const int lane = tid & 31;
    const int w    = tid >> 5;
    #pragma unroll
    for (int off = 16; off; off >>= 1)
        ssum += __shfl_xor_sync(0xFFFFFFFFu, ssum, off);
    if (lane == 0) warpsum[w] = ssum;
    __syncthreads();

    if (tid == 0) {
        float bsum = 0.0f;
        #pragma unroll
        for (int j = 0; j < 8; ++j) bsum += warpsum[j];
        // Deterministic fixed-point accumulation (order-independent).
        unsigned long long q = (unsigned long long)llrintf(bsum * FPSCALE);
        atomicAdd(&g_isum, q);
        __threadfence();
        int c = atomicAdd(&g_counter, 1);
        if (c == (int)gridDim.x - 1) {
            unsigned long long tot = atomicAdd(&g_isum, 0ULL);
            out[0] = (float)((double)tot * (1.0 / (double)FPSCALE) * (double)scale);
            g_isum = 0ULL;                   // reset for next graph replay
            __threadfence();
            g_counter = 0;
        }
    }
}

extern "C" void kernel_launch(void* const* d_in, const int* in_sizes, int n_in,
                              void* d_out, int out_size) {
    const float* inp = (const float*)d_in[0];   // input, [B,1] fp32
    const float* tm  = (const float*)d_in[1];   // gdt_ts, [B]  fp32

    const int B = in_sizes[0];
    const int K = B / DEC;
    const int G = K - 1;                        // reference skips the last group
    const double N = (double)G * DEC * (DEC - 1);
    const float scale = (float)(2.0 / N);       // x2: unordered -> ordered pairs

    rank_loss_fused<<<2 * G, 256>>>(inp, tm, (float*)d_out, scale);
}

// round 12
// speedup vs baseline: 1.1875x; 1.0208x over previous
#include <cuda_runtime.h>

#define DEC 256
#define CS  521               // copy stride in floats: ≡1 (mod 4) -> conflict-free
#define FPSCALE 16777216.0f   // 2^24 fixed-point for deterministic accumulation

// Deterministic global accumulator (integer adds commute exactly) + ticket.
__device__ unsigned long long g_isum    = 0ULL;
__device__ int                g_counter = 0;

// One pair: no/nt hold NEGATED own values, wo/wt positive neighbor values.
// dO_ = o_j - o_i, dt_ = t_j - t_i (jointly negated vs reference; the
// sign-xor product and |dt| are invariant; dt==0 has weight 0).
#define PT(r, WO, WT)                                                        \
    {                                                                        \
        float dO_ = (WO) + no##r;                                            \
        float dt_ = (WT) + nt##r;                                            \
        float x_  = __uint_as_float(__float_as_uint(dO_) ^                   \
                                    (__float_as_uint(dt_) & 0x80000000u));   \
        float m_  = (fabsf(dt_) > 0.1f) ? 1.0f : 0.0f;                       \
        float h_  = fmaxf(x_ + 1.0f, 0.0f);                                  \
        a##r = fmaf(h_, m_, a##r);                                           \
    }

// One k-step: 4 pairs on rotated slots, then refill the retiring slot.
#define STEPR(S0, S1, S2, S3, OFF)                                           \
    PT(0, wo##S0, wt##S0)                                                    \
    PT(1, wo##S1, wt##S1)                                                    \
    PT(2, wo##S2, wt##S2)                                                    \
    PT(3, wo##S3, wt##S3)                                                    \
    wo##S0 = pw_o[OFF];                                                      \
    wt##S0 = pw_t[OFF];

__global__ void __launch_bounds__(256)
rank_loss_fused(const float* __restrict__ inp, const float* __restrict__ tm,
                float* __restrict__ out, float scale) {
    __shared__ float sh_o[4 * CS];   // 4 replicated copies of o (dup to idx 511)
    __shared__ float sh_t[4 * CS];
    __shared__ float warpsum[8];

    const int g    = blockIdx.x >> 1;   // group
    const int half = blockIdx.x & 1;    // k-tile: 0 -> k in [1..64], 1 -> [65..128]
    const int tid  = threadIdx.x;
    const int base = g * DEC;

    {
        float o = inp[base + tid];
        float t = tm[base + tid];
        float* so = &sh_o[tid];
        float* st = &sh_t[tid];
        #pragma unroll
        for (int c = 0; c < 4; ++c) {          // all offsets compile-time
            so[c * CS]       = o;
            so[c * CS + DEC] = o;
            st[c * CS]       = t;
            st[c * CS + DEC] = t;
        }
    }
    __syncthreads();

    // 4 k-subranges (16 each) x 64 row-quads.
    const int s    = tid >> 6;
    const int tau  = tid & 63;
    const int b    = tau * 4;                  // first owned row
    const int k0   = half * 64 + s * 16 + 1;   // k in [k0, k0+15]
    const int copy = (tid >> 3) & 3;           // lane-octet -> copy (bank residue)

    const float* pown_o = &sh_o[copy * CS + b];
    const float* pown_t = &sh_t[copy * CS + b];
    const float* pw_o   = pown_o + k0;         // window base; offsets immediate
    const float* pw_t   = pown_t + k0;

    // Own rows, negated once.
    const float no0 = -pown_o[0], nt0 = -pown_t[0];
    const float no1 = -pown_o[1], nt1 = -pown_t[1];
    const float no2 = -pown_o[2], nt2 = -pown_t[2];
    const float no3 = -pown_o[3], nt3 = -pown_t[3];

    // Window slots (named registers; rotation is purely positional).
    float wo0 = pw_o[0], wt0 = pw_t[0];
    float wo1 = pw_o[1], wt1 = pw_t[1];
    float wo2 = pw_o[2], wt2 = pw_t[2];
    float wo3 = pw_o[3], wt3 = pw_t[3];

    float a0 = 0.0f, a1 = 0.0f, a2 = 0.0f, a3 = 0.0f;

    STEPR(0, 1, 2, 3, 4)   STEPR(1, 2, 3, 0, 5)
    STEPR(2, 3, 0, 1, 6)   STEPR(3, 0, 1, 2, 7)
    STEPR(0, 1, 2, 3, 8)   STEPR(1, 2, 3, 0, 9)
    STEPR(2, 3, 0, 1, 10)  STEPR(3, 0, 1, 2, 11)
    STEPR(0, 1, 2, 3, 12)  STEPR(1, 2, 3, 0, 13)
    STEPR(2, 3, 0, 1, 14)  STEPR(3, 0, 1, 2, 15)
    STEPR(0, 1, 2, 3, 16)  STEPR(1, 2, 3, 0, 17)
    STEPR(2, 3, 0, 1, 18)
    // Step 16 (k = k0+15): slots 3,0,1,2 hold +15..+18. Only k=128
    // (half==1 && s==3) is restricted to rows<128 <=> inactive iff tid>=224.
    if (!(half && tid >= 224)) {
        PT(0, wo3, wt3)
        PT(1, wo0, wt0)
        PT(2, wo1, wt1)
        PT(3, wo2, wt2)
    }

    // Block reduction (fixed order).
    float ssum = (a0 + a1) + (a2 + a3);
    const int lane = tid & 31;
    const int w    = tid >> 5;
    #pragma unroll
    for (int off = 16; off; off >>= 1)
        ssum += __shfl_xor_sync(0xFFFFFFFFu, ssum, off);
    if (lane == 0) warpsum[w] = ssum;
    __syncthreads();

    if (tid == 0) {
        float bsum = 0.0f;
        #pragma unroll
        for (int j = 0; j < 8; ++j) bsum += warpsum[j];
        // Deterministic fixed-point accumulation (order-independent).
        unsigned long long q = (unsigned long long)llrintf(bsum * FPSCALE);
        atomicAdd(&g_isum, q);
        __threadfence();
        int c = atomicAdd(&g_counter, 1);
        if (c == (int)gridDim.x - 1) {
            unsigned long long tot = atomicAdd(&g_isum, 0ULL);
            out[0] = (float)((double)tot * (1.0 / (double)FPSCALE) * (double)scale);
            g_isum = 0ULL;                   // reset for next graph replay
            __threadfence();
            g_counter = 0;
        }
    }
}

extern "C" void kernel_launch(void* const* d_in, const int* in_sizes, int n_in,
                              void* d_out, int out_size) {
    const float* inp = (const float*)d_in[0];   // input, [B,1] fp32
    const float* tm  = (const float*)d_in[1];   // gdt_ts, [B]  fp32

    const int B = in_sizes[0];
    const int K = B / DEC;
    const int G = K - 1;                        // reference skips the last group
    const double N = (double)G * DEC * (DEC - 1);
    const float scale = (float)(2.0 / N);       // x2: unordered -> ordered pairs

    rank_loss_fused<<<2 * G, 256>>>(inp, tm, (float*)d_out, scale);
}